// round 10
// baseline (speedup 1.0000x reference)
#include <cuda_runtime.h>
#include <cuda_bf16.h>
#include <cstdint>

#define BB 2
#define TT 2048
#define CCH 1024
#define HH 16
#define DD 64
#define MTOK (BB*TT)          // 4096 tokens
#define GK   1024

// ---------------------------------------------------------------------------
// Scratch (allocation-free rule: __device__ globals), all bf16 hi/lo pairs
// ---------------------------------------------------------------------------
__device__ __nv_bfloat16 g_hs_h[MTOK*CCH],  g_hs_l[MTOK*CCH];
__device__ __nv_bfloat16 g_Wqk_h[CCH*CCH],  g_Wqk_l[CCH*CCH];
__device__ __nv_bfloat16 g_Wv_h [CCH*CCH],  g_Wv_l [CCH*CCH];
__device__ __nv_bfloat16 g_Wo_h [CCH*CCH],  g_Wo_l [CCH*CCH];
__device__ __nv_bfloat16 g_qk_h[MTOK*CCH],  g_qk_l[MTOK*CCH];
__device__ __nv_bfloat16 g_v_h [MTOK*CCH],  g_v_l [MTOK*CCH];
__device__ __nv_bfloat16 g_y_h [MTOK*CCH],  g_y_l [MTOK*CCH];

// ===========================================================================
// Helpers
// ===========================================================================
__device__ __forceinline__ void split_bf16(float x,
    __nv_bfloat16& h, __nv_bfloat16& l)
{
    h = __float2bfloat16_rn(x);
    l = __float2bfloat16_rn(x - __bfloat162float(h));
}

__device__ __forceinline__ void mma_bf16(float c[4],
    const unsigned int a[4], const unsigned int b[2])
{
    asm volatile(
        "mma.sync.aligned.m16n8k16.row.col.f32.bf16.bf16.f32 "
        "{%0,%1,%2,%3}, {%4,%5,%6,%7}, {%8,%9}, {%0,%1,%2,%3};"
        : "+f"(c[0]), "+f"(c[1]), "+f"(c[2]), "+f"(c[3])
        : "r"(a[0]), "r"(a[1]), "r"(a[2]), "r"(a[3]), "r"(b[0]), "r"(b[1]));
}

__device__ __forceinline__ void ldsm4(const __nv_bfloat16* base, int row0,
    int kc, int lane, int stride, unsigned int r[4])
{
    const __nv_bfloat16* p = base + (row0 + (lane & 15)) * stride
                                  + kc + ((lane >> 4) << 3);
    unsigned int addr = (unsigned int)__cvta_generic_to_shared(p);
    asm volatile("ldmatrix.sync.aligned.m8n8.x4.shared.b16 {%0,%1,%2,%3}, [%4];"
        : "=r"(r[0]), "=r"(r[1]), "=r"(r[2]), "=r"(r[3]) : "r"(addr));
}

__device__ __forceinline__ void ldsm2(const __nv_bfloat16* base, int row0,
    int kc, int lane, int stride, unsigned int r[2])
{
    const __nv_bfloat16* p = base + (row0 + (lane & 7)) * stride
                                  + kc + (((lane >> 3) & 1) << 3);
    unsigned int addr = (unsigned int)__cvta_generic_to_shared(p);
    asm volatile("ldmatrix.sync.aligned.m8n8.x2.shared.b16 {%0,%1}, [%2];"
        : "=r"(r[0]), "=r"(r[1]) : "r"(addr));
}

// transposed B-fragment load: smem tile is [k][n] row-major (rows = k)
__device__ __forceinline__ void ldsm2t(const __nv_bfloat16* base, int k0,
    int n0, int lane, int stride, unsigned int r[2])
{
    const __nv_bfloat16* p = base
        + (k0 + (lane & 7) + ((lane >> 3) & 1) * 8) * stride + n0;
    unsigned int addr = (unsigned int)__cvta_generic_to_shared(p);
    asm volatile("ldmatrix.sync.aligned.m8n8.x2.trans.shared.b16 {%0,%1}, [%2];"
        : "=r"(r[0]), "=r"(r[1]) : "r"(addr));
}

// ===========================================================================
// Fused elementwise fp32 -> bf16 hi/lo split: hs + 3 weight matrices
// ===========================================================================
#define N4_HS (MTOK*CCH/4)
#define N4_W  (CCH*CCH/4)
#define N4_TOT (N4_HS + 3*N4_W)

__global__ void split4_kernel(
    const float4* __restrict__ hs, const float4* __restrict__ wqk,
    const float4* __restrict__ wv, const float4* __restrict__ wo,
    __nv_bfloat162* __restrict__ hs_h, __nv_bfloat162* __restrict__ hs_l,
    __nv_bfloat162* __restrict__ wqk_h, __nv_bfloat162* __restrict__ wqk_l,
    __nv_bfloat162* __restrict__ wv_h, __nv_bfloat162* __restrict__ wv_l,
    __nv_bfloat162* __restrict__ wo_h, __nv_bfloat162* __restrict__ wo_l)
{
    int i = blockIdx.x * blockDim.x + threadIdx.x;
    if (i >= N4_TOT) return;
    const float4* src; __nv_bfloat162 *dh, *dl; int off;
    if (i < N4_HS)            { src = hs;  dh = hs_h;  dl = hs_l;  off = i; }
    else if (i < N4_HS+N4_W)  { src = wqk; dh = wqk_h; dl = wqk_l; off = i - N4_HS; }
    else if (i < N4_HS+2*N4_W){ src = wv;  dh = wv_h;  dl = wv_l;  off = i - N4_HS - N4_W; }
    else                      { src = wo;  dh = wo_h;  dl = wo_l;  off = i - N4_HS - 2*N4_W; }
    float4 v = src[off];
    float f[4] = {v.x, v.y, v.z, v.w};
    __nv_bfloat16 h[4], l[4];
#pragma unroll
    for (int q = 0; q < 4; q++) split_bf16(f[q], h[q], l[q]);
    dh[2*off    ] = __nv_bfloat162(h[0], h[1]);
    dh[2*off + 1] = __nv_bfloat162(h[2], h[3]);
    dl[2*off    ] = __nv_bfloat162(l[0], l[1]);
    dl[2*off + 1] = __nv_bfloat162(l[2], l[3]);
}

// ===========================================================================
// bf16x3 tensor-core GEMM v3: 4 warps, 64x64 warp tiles (smem-BW-optimal).
//   C[M,N] = (Ah+Al)@(Wh+Wl)^T + bias (3-term split).
// CTA 128x128, BK=32, 128 threads, 2-stage cp.async, 2 CTAs/SM.
// ===========================================================================
#define SSTR 40
#define KTILE (128*SSTR)
#define STAGE_ELEMS (4*KTILE)
#define GEMM_SMEM (2*STAGE_ELEMS*2)     // 80KB

__global__ __launch_bounds__(128, 2) void gemm_pre_kernel(
    const __nv_bfloat16* __restrict__ Ah_g, const __nv_bfloat16* __restrict__ Al_g,
    const __nv_bfloat16* __restrict__ Wh_g, const __nv_bfloat16* __restrict__ Wl_g,
    const float* __restrict__ bias, float* __restrict__ Cout,
    __nv_bfloat16* __restrict__ outh, __nv_bfloat16* __restrict__ outl)
{
    extern __shared__ __nv_bfloat16 smem[];

    const int tid  = threadIdx.x;
    const int wid  = tid >> 5;           // 0..3
    const int lane = tid & 31;
    const int g    = lane >> 2;
    const int t4   = lane & 3;
    const int m0   = blockIdx.y * 128;
    const int n0   = blockIdx.x * 128;
    const int wm   = (wid & 1) * 64;     // warp m offset
    const int wn   = (wid >> 1) * 64;    // warp n offset

    const __nv_bfloat16* srcs[4] = {Ah_g, Al_g, Wh_g, Wl_g};

    float acc[4][8][4];
#pragma unroll
    for (int i = 0; i < 4; i++)
#pragma unroll
        for (int j = 0; j < 8; j++)
#pragma unroll
            for (int r = 0; r < 4; r++) acc[i][j][r] = 0.f;

    auto issue_stage = [&](int kt, int s) {
        const int kk = kt * 32;
#pragma unroll
        for (int p = 0; p < 16; p++) {
            int idx  = tid + 128*p;          // 0..2047
            int tile = idx >> 9;             // 0..3
            int rem  = idx & 511;
            int r    = rem >> 2;             // 0..127
            int c    = rem & 3;              // 0..3 (16B chunks)
            int grow = ((tile < 2) ? m0 : n0) + r;
            const __nv_bfloat16* src = srcs[tile] + (size_t)grow * GK + kk + c*8;
            __nv_bfloat16* dst = smem + s*STAGE_ELEMS + tile*KTILE + r*SSTR + c*8;
            unsigned int daddr = (unsigned int)__cvta_generic_to_shared(dst);
            asm volatile("cp.async.cg.shared.global [%0], [%1], 16;\n"
                         :: "r"(daddr), "l"(src));
        }
        asm volatile("cp.async.commit_group;\n");
    };

    issue_stage(0, 0);

    const int nk = GK / 32;
    for (int kt = 0; kt < nk; kt++) {
        const int s = kt & 1;
        const bool more = (kt + 1 < nk);
        if (more) {
            issue_stage(kt + 1, s ^ 1);
            asm volatile("cp.async.wait_group 1;\n");
        } else {
            asm volatile("cp.async.wait_group 0;\n");
        }
        __syncthreads();

        const __nv_bfloat16* sAh = smem + s*STAGE_ELEMS;
        const __nv_bfloat16* sAl = sAh + KTILE;
        const __nv_bfloat16* sWh = sAh + 2*KTILE;
        const __nv_bfloat16* sWl = sAh + 3*KTILE;

#pragma unroll
        for (int ks = 0; ks < 32; ks += 16) {
            unsigned int ah[4][4], al[4][4], bh[8][2], bl[8][2];
#pragma unroll
            for (int i = 0; i < 4; i++) {
                ldsm4(sAh, wm + i*16, ks, lane, SSTR, ah[i]);
                ldsm4(sAl, wm + i*16, ks, lane, SSTR, al[i]);
            }
#pragma unroll
            for (int jj = 0; jj < 4; jj++) {     // each ldsm4 covers 2 n8 tiles
                unsigned int q[4];
                ldsm4(sWh, wn + jj*16, ks, lane, SSTR, q);
                bh[2*jj][0] = q[0]; bh[2*jj][1] = q[2];
                bh[2*jj+1][0] = q[1]; bh[2*jj+1][1] = q[3];
                ldsm4(sWl, wn + jj*16, ks, lane, SSTR, q);
                bl[2*jj][0] = q[0]; bl[2*jj][1] = q[2];
                bl[2*jj+1][0] = q[1]; bl[2*jj+1][1] = q[3];
            }
#pragma unroll
            for (int i = 0; i < 4; i++)
#pragma unroll
                for (int j = 0; j < 8; j++) {
                    mma_bf16(acc[i][j], ah[i], bh[j]);
                    mma_bf16(acc[i][j], ah[i], bl[j]);
                    mma_bf16(acc[i][j], al[i], bh[j]);
                }
        }
        __syncthreads();
    }

    // epilogue
#pragma unroll
    for (int i = 0; i < 4; i++)
#pragma unroll
        for (int j = 0; j < 8; j++) {
            const int r = m0 + wm + i*16 + g;
            const int c = n0 + wn + j*8 + t4*2;
            const float b0v = bias[c], b1v = bias[c+1];
            float v00 = acc[i][j][0] + b0v, v01 = acc[i][j][1] + b1v;
            float v10 = acc[i][j][2] + b0v, v11 = acc[i][j][3] + b1v;
            if (outl) {
                __nv_bfloat16 h0,l0,h1,l1,h2,l2,h3,l3;
                split_bf16(v00, h0, l0); split_bf16(v01, h1, l1);
                split_bf16(v10, h2, l2); split_bf16(v11, h3, l3);
                *(__nv_bfloat162*)&outh[(size_t)r      *CCH + c] = __nv_bfloat162(h0, h1);
                *(__nv_bfloat162*)&outh[(size_t)(r + 8)*CCH + c] = __nv_bfloat162(h2, h3);
                *(__nv_bfloat162*)&outl[(size_t)r      *CCH + c] = __nv_bfloat162(l0, l1);
                *(__nv_bfloat162*)&outl[(size_t)(r + 8)*CCH + c] = __nv_bfloat162(l2, l3);
            } else {
                float2 w0 = {v00, v01}, w1 = {v10, v11};
                *(float2*)&Cout[(size_t)r       * CCH + c] = w0;
                *(float2*)&Cout[(size_t)(r + 8) * CCH + c] = w1;
            }
        }
}

// ===========================================================================
// Tensor-core flash attention on pre-split bf16 hi/lo operands.
// (reverted to R6 config — best measured: 64-query CTA, 4 warps)
// ===========================================================================
#define ASTR 72
#define ATILE (64*ASTR)
#define ATTN_SMEM (6*ATILE*2)     // 55296 bytes

__global__ __launch_bounds__(128) void attn_mma_kernel(
    const __nv_bfloat16* __restrict__ qkh, const __nv_bfloat16* __restrict__ qkl,
    const __nv_bfloat16* __restrict__ vgh, const __nv_bfloat16* __restrict__ vgl,
    __nv_bfloat16* __restrict__ yh, __nv_bfloat16* __restrict__ yl)
{
    extern __shared__ __nv_bfloat16 smA[];
    __nv_bfloat16* Qh = smA;
    __nv_bfloat16* Ql = smA +   ATILE;
    __nv_bfloat16* Kh = smA + 2*ATILE;
    __nv_bfloat16* Kl = smA + 3*ATILE;
    __nv_bfloat16* Vh = smA + 4*ATILE;   // [t][d]
    __nv_bfloat16* Vl = smA + 5*ATILE;

    const int tid  = threadIdx.x;
    const int wid  = tid >> 5;
    const int lane = tid & 31;
    const int g    = lane >> 2;
    const int t4   = lane & 3;
    const int qi = blockIdx.x;
    const int bh = blockIdx.y;
    const int b  = bh / HH, h = bh % HH;
    const int q0 = qi * 64;
    const size_t base = ((size_t)b * TT) * CCH + (size_t)h * DD;

    // ---- load Q tile (bare 16B copies) ----
#pragma unroll
    for (int p = 0; p < 4; p++) {
        int idx = tid + 128*p;           // 0..511
        int r   = idx >> 3;              // 0..63
        int c8  = (idx & 7) * 8;         // 0..56
        size_t gg = base + (size_t)(q0 + r)*CCH + c8;
        *(uint4*)&Qh[r*ASTR + c8] = *(const uint4*)&qkh[gg];
        *(uint4*)&Ql[r*ASTR + c8] = *(const uint4*)&qkl[gg];
    }

    float m0r = -1e30f, m1r = -1e30f, l0r = 0.f, l1r = 0.f;
    float o[8][4];
#pragma unroll
    for (int j = 0; j < 8; j++)
#pragma unroll
        for (int r = 0; r < 4; r++) o[j][r] = 0.f;

    for (int kv = 0; kv <= qi; kv++) {
        __syncthreads();   // prior-iter readers done (first iter covers Q fill)
#pragma unroll
        for (int p = 0; p < 4; p++) {
            int idx = tid + 128*p;
            int r   = idx >> 3;
            int c8  = (idx & 7) * 8;
            size_t gg = base + (size_t)(kv*64 + r)*CCH + c8;
            *(uint4*)&Kh[r*ASTR + c8] = *(const uint4*)&qkh[gg];
            *(uint4*)&Kl[r*ASTR + c8] = *(const uint4*)&qkl[gg];
            *(uint4*)&Vh[r*ASTR + c8] = *(const uint4*)&vgh[gg];
            *(uint4*)&Vl[r*ASTR + c8] = *(const uint4*)&vgl[gg];
        }
        __syncthreads();

        // ---- S = Q @ K^T (split x3) ----
        float s[8][4];
#pragma unroll
        for (int j = 0; j < 8; j++)
#pragma unroll
            for (int r = 0; r < 4; r++) s[j][r] = 0.f;

#pragma unroll
        for (int ks = 0; ks < 4; ks++) {
            unsigned int ah[4], al[4];
            ldsm4(Qh, wid*16, ks*16, lane, ASTR, ah);
            ldsm4(Ql, wid*16, ks*16, lane, ASTR, al);
#pragma unroll
            for (int j = 0; j < 8; j++) {
                unsigned int kbh[2], kbl[2];
                ldsm2(Kh, j*8, ks*16, lane, ASTR, kbh);
                ldsm2(Kl, j*8, ks*16, lane, ASTR, kbl);
                mma_bf16(s[j], ah, kbh);
                mma_bf16(s[j], ah, kbl);
                mma_bf16(s[j], al, kbh);
            }
        }

        // ---- scale + causal mask ----
        const float scale = 0.125f;
        const int row0 = wid*16 + g;
        const int row1 = row0 + 8;
        if (kv == qi) {
#pragma unroll
            for (int j = 0; j < 8; j++) {
                const int c0 = j*8 + 2*t4, c1 = c0 + 1;
                s[j][0] = (c0 > row0) ? -1e30f : s[j][0]*scale;
                s[j][1] = (c1 > row0) ? -1e30f : s[j][1]*scale;
                s[j][2] = (c0 > row1) ? -1e30f : s[j][2]*scale;
                s[j][3] = (c1 > row1) ? -1e30f : s[j][3]*scale;
            }
        } else {
#pragma unroll
            for (int j = 0; j < 8; j++)
#pragma unroll
                for (int r = 0; r < 4; r++) s[j][r] *= scale;
        }

        // ---- online softmax (quad reductions) ----
        float mx0 = -1e30f, mx1 = -1e30f;
#pragma unroll
        for (int j = 0; j < 8; j++) {
            mx0 = fmaxf(mx0, fmaxf(s[j][0], s[j][1]));
            mx1 = fmaxf(mx1, fmaxf(s[j][2], s[j][3]));
        }
        mx0 = fmaxf(mx0, __shfl_xor_sync(0xffffffffu, mx0, 1));
        mx0 = fmaxf(mx0, __shfl_xor_sync(0xffffffffu, mx0, 2));
        mx1 = fmaxf(mx1, __shfl_xor_sync(0xffffffffu, mx1, 1));
        mx1 = fmaxf(mx1, __shfl_xor_sync(0xffffffffu, mx1, 2));

        const float mn0 = fmaxf(m0r, mx0), mn1 = fmaxf(m1r, mx1);
        const float cr0 = __expf(m0r - mn0), cr1 = __expf(m1r - mn1);
        m0r = mn0; m1r = mn1;

        float sum0 = 0.f, sum1 = 0.f;
#pragma unroll
        for (int j = 0; j < 8; j++) {
            s[j][0] = __expf(s[j][0] - mn0);
            s[j][1] = __expf(s[j][1] - mn0);
            s[j][2] = __expf(s[j][2] - mn1);
            s[j][3] = __expf(s[j][3] - mn1);
            sum0 += s[j][0] + s[j][1];
            sum1 += s[j][2] + s[j][3];
        }
        sum0 += __shfl_xor_sync(0xffffffffu, sum0, 1);
        sum0 += __shfl_xor_sync(0xffffffffu, sum0, 2);
        sum1 += __shfl_xor_sync(0xffffffffu, sum1, 1);
        sum1 += __shfl_xor_sync(0xffffffffu, sum1, 2);
        l0r = l0r*cr0 + sum0;
        l1r = l1r*cr1 + sum1;

#pragma unroll
        for (int j = 0; j < 8; j++) {
            o[j][0] *= cr0; o[j][1] *= cr0;
            o[j][2] *= cr1; o[j][3] *= cr1;
        }

        // ---- O += P @ V (split x3), P frags in registers, V via ldsm.trans ----
#pragma unroll
        for (int c = 0; c < 4; c++) {
            unsigned int aPh[4], aPl[4];
#pragma unroll
            for (int half = 0; half < 2; half++) {
                const int jt = 2*c + half;
                __nv_bfloat16 h0,l0,h1,l1,h2,l2,h3,l3;
                split_bf16(s[jt][0], h0, l0);
                split_bf16(s[jt][1], h1, l1);
                split_bf16(s[jt][2], h2, l2);
                split_bf16(s[jt][3], h3, l3);
                __nv_bfloat162 H01(h0, h1), H23(h2, h3), L01(l0, l1), L23(l2, l3);
                aPh[2*half    ] = *(unsigned int*)&H01;
                aPh[2*half + 1] = *(unsigned int*)&H23;
                aPl[2*half    ] = *(unsigned int*)&L01;
                aPl[2*half + 1] = *(unsigned int*)&L23;
            }
#pragma unroll
            for (int j = 0; j < 8; j++) {
                unsigned int vbh[2], vbl[2];
                ldsm2t(Vh, c*16, j*8, lane, ASTR, vbh);
                ldsm2t(Vl, c*16, j*8, lane, ASTR, vbl);
                mma_bf16(o[j], aPh, vbh);
                mma_bf16(o[j], aPh, vbl);
                mma_bf16(o[j], aPl, vbh);
            }
        }
    }

    // ---- normalize + write y as bf16 hi/lo ----
    const float inv0 = 1.f / l0r, inv1 = 1.f / l1r;
    const int r0 = q0 + wid*16 + g;
    const int r1 = r0 + 8;
#pragma unroll
    for (int j = 0; j < 8; j++) {
        const int c = j*8 + 2*t4;
        float v00 = o[j][0]*inv0, v01 = o[j][1]*inv0;
        float v10 = o[j][2]*inv1, v11 = o[j][3]*inv1;
        __nv_bfloat16 h0,l0,h1,l1,h2,l2,h3,l3;
        split_bf16(v00, h0, l0); split_bf16(v01, h1, l1);
        split_bf16(v10, h2, l2); split_bf16(v11, h3, l3);
        *(__nv_bfloat162*)&yh[base + (size_t)r0*CCH + c] = __nv_bfloat162(h0, h1);
        *(__nv_bfloat162*)&yh[base + (size_t)r1*CCH + c] = __nv_bfloat162(h2, h3);
        *(__nv_bfloat162*)&yl[base + (size_t)r0*CCH + c] = __nv_bfloat162(l0, l1);
        *(__nv_bfloat162*)&yl[base + (size_t)r1*CCH + c] = __nv_bfloat162(l2, l3);
    }
}

// ---------------------------------------------------------------------------
extern "C" void kernel_launch(void* const* d_in, const int* in_sizes, int n_in,
                              void* d_out, int out_size)
{
    const float* hs  = (const float*)d_in[0];
    const float* Wqk = (const float*)d_in[1];
    const float* bqk = (const float*)d_in[2];
    const float* Wv  = (const float*)d_in[3];
    const float* bv  = (const float*)d_in[4];
    const float* Wo  = (const float*)d_in[5];
    const float* bo  = (const float*)d_in[6];
    float* out = (float*)d_out;

    __nv_bfloat16 *hs_h,*hs_l,*wqk_h,*wqk_l,*wv_h,*wv_l,*wo_h,*wo_l;
    __nv_bfloat16 *qk_h,*qk_l,*v_h,*v_l,*y_h,*y_l;
    cudaGetSymbolAddress((void**)&hs_h, g_hs_h);   cudaGetSymbolAddress((void**)&hs_l, g_hs_l);
    cudaGetSymbolAddress((void**)&wqk_h, g_Wqk_h); cudaGetSymbolAddress((void**)&wqk_l, g_Wqk_l);
    cudaGetSymbolAddress((void**)&wv_h, g_Wv_h);   cudaGetSymbolAddress((void**)&wv_l, g_Wv_l);
    cudaGetSymbolAddress((void**)&wo_h, g_Wo_h);   cudaGetSymbolAddress((void**)&wo_l, g_Wo_l);
    cudaGetSymbolAddress((void**)&qk_h, g_qk_h);   cudaGetSymbolAddress((void**)&qk_l, g_qk_l);
    cudaGetSymbolAddress((void**)&v_h, g_v_h);     cudaGetSymbolAddress((void**)&v_l, g_v_l);
    cudaGetSymbolAddress((void**)&y_h, g_y_h);     cudaGetSymbolAddress((void**)&y_l, g_y_l);

    cudaFuncSetAttribute(attn_mma_kernel,
                         cudaFuncAttributeMaxDynamicSharedMemorySize, ATTN_SMEM);
    cudaFuncSetAttribute(gemm_pre_kernel,
                         cudaFuncAttributeMaxDynamicSharedMemorySize, GEMM_SMEM);

    // fused pre-split of all fp32 inputs
    split4_kernel<<<(N4_TOT+255)/256, 256>>>(
        (const float4*)hs, (const float4*)Wqk, (const float4*)Wv, (const float4*)Wo,
        (__nv_bfloat162*)hs_h, (__nv_bfloat162*)hs_l,
        (__nv_bfloat162*)wqk_h, (__nv_bfloat162*)wqk_l,
        (__nv_bfloat162*)wv_h, (__nv_bfloat162*)wv_l,
        (__nv_bfloat162*)wo_h, (__nv_bfloat162*)wo_l);

    dim3 ggrid(CCH/128, MTOK/128);   // (8, 32)
    gemm_pre_kernel<<<ggrid, 128, GEMM_SMEM>>>(hs_h, hs_l, wqk_h, wqk_l,
        bqk, nullptr, qk_h, qk_l);
    gemm_pre_kernel<<<ggrid, 128, GEMM_SMEM>>>(hs_h, hs_l, wv_h, wv_l,
        bv, nullptr, v_h, v_l);

    attn_mma_kernel<<<dim3(TT/64, BB*HH), 128, ATTN_SMEM>>>(qk_h, qk_l,
        v_h, v_l, y_h, y_l);

    gemm_pre_kernel<<<ggrid, 128, GEMM_SMEM>>>(y_h, y_l, wo_h, wo_l,
        bo, out, nullptr, nullptr);
}

// round 11
// speedup vs baseline: 1.4626x; 1.4626x over previous
#include <cuda_runtime.h>
#include <cuda_fp16.h>
#include <cstdint>

#define BB 2
#define TT 2048
#define CCH 1024
#define HH 16
#define DD 64
#define MTOK (BB*TT)          // 4096 tokens
#define GK   1024

// ---------------------------------------------------------------------------
// Scratch (allocation-free rule: __device__ globals), fp16
// ---------------------------------------------------------------------------
__device__ __half g_hs_h[MTOK*CCH],  g_hs_l[MTOK*CCH];
__device__ __half g_Wqk_h[CCH*CCH];
__device__ __half g_Wv_h [CCH*CCH];
__device__ __half g_Wo_h [CCH*CCH];
__device__ __half g_qk_h[MTOK*CCH], g_qk_l[MTOK*CCH];
__device__ __half g_v_h [MTOK*CCH];
__device__ __half g_y_h [MTOK*CCH], g_y_l [MTOK*CCH];

// ===========================================================================
// Helpers
// ===========================================================================
__device__ __forceinline__ void split_fp16(float x, __half& h, __half& l)
{
    h = __float2half_rn(x);
    l = __float2half_rn(x - __half2float(h));
}

__device__ __forceinline__ void mma_fp16(float c[4],
    const unsigned int a[4], const unsigned int b[2])
{
    asm volatile(
        "mma.sync.aligned.m16n8k16.row.col.f32.f16.f16.f32 "
        "{%0,%1,%2,%3}, {%4,%5,%6,%7}, {%8,%9}, {%0,%1,%2,%3};"
        : "+f"(c[0]), "+f"(c[1]), "+f"(c[2]), "+f"(c[3])
        : "r"(a[0]), "r"(a[1]), "r"(a[2]), "r"(a[3]), "r"(b[0]), "r"(b[1]));
}

__device__ __forceinline__ void ldsm4(const __half* base, int row0,
    int kc, int lane, int stride, unsigned int r[4])
{
    const __half* p = base + (row0 + (lane & 15)) * stride
                           + kc + ((lane >> 4) << 3);
    unsigned int addr = (unsigned int)__cvta_generic_to_shared(p);
    asm volatile("ldmatrix.sync.aligned.m8n8.x4.shared.b16 {%0,%1,%2,%3}, [%4];"
        : "=r"(r[0]), "=r"(r[1]), "=r"(r[2]), "=r"(r[3]) : "r"(addr));
}

__device__ __forceinline__ void ldsm2(const __half* base, int row0,
    int kc, int lane, int stride, unsigned int r[2])
{
    const __half* p = base + (row0 + (lane & 7)) * stride
                           + kc + (((lane >> 3) & 1) << 3);
    unsigned int addr = (unsigned int)__cvta_generic_to_shared(p);
    asm volatile("ldmatrix.sync.aligned.m8n8.x2.shared.b16 {%0,%1}, [%2];"
        : "=r"(r[0]), "=r"(r[1]) : "r"(addr));
}

// transposed B-fragment load: smem tile is [k][n] row-major (rows = k)
__device__ __forceinline__ void ldsm2t(const __half* base, int k0,
    int n0, int lane, int stride, unsigned int r[2])
{
    const __half* p = base
        + (k0 + (lane & 7) + ((lane >> 3) & 1) * 8) * stride + n0;
    unsigned int addr = (unsigned int)__cvta_generic_to_shared(p);
    asm volatile("ldmatrix.sync.aligned.m8n8.x2.trans.shared.b16 {%0,%1}, [%2];"
        : "=r"(r[0]), "=r"(r[1]) : "r"(addr));
}

// ===========================================================================
// Fused split: hs -> (h,l); weights -> h only
// ===========================================================================
#define N4_HS (MTOK*CCH/4)
#define N4_W  (CCH*CCH/4)
#define N4_TOT (N4_HS + 3*N4_W)

__global__ void split4_kernel(
    const float4* __restrict__ hs, const float4* __restrict__ wqk,
    const float4* __restrict__ wv, const float4* __restrict__ wo,
    __half2* __restrict__ hs_h, __half2* __restrict__ hs_l,
    __half2* __restrict__ wqk_h, __half2* __restrict__ wv_h,
    __half2* __restrict__ wo_h)
{
    int i = blockIdx.x * blockDim.x + threadIdx.x;
    if (i >= N4_TOT) return;
    const float4* src; __half2 *dh, *dl; int off;
    if (i < N4_HS)            { src = hs;  dh = hs_h;  dl = hs_l;  off = i; }
    else if (i < N4_HS+N4_W)  { src = wqk; dh = wqk_h; dl = nullptr; off = i - N4_HS; }
    else if (i < N4_HS+2*N4_W){ src = wv;  dh = wv_h;  dl = nullptr; off = i - N4_HS - N4_W; }
    else                      { src = wo;  dh = wo_h;  dl = nullptr; off = i - N4_HS - 2*N4_W; }
    float4 v = src[off];
    float f[4] = {v.x, v.y, v.z, v.w};
    __half h[4], l[4];
#pragma unroll
    for (int q = 0; q < 4; q++) split_fp16(f[q], h[q], l[q]);
    dh[2*off    ] = __halves2half2(h[0], h[1]);
    dh[2*off + 1] = __halves2half2(h[2], h[3]);
    if (dl) {
        dl[2*off    ] = __halves2half2(l[0], l[1]);
        dl[2*off + 1] = __halves2half2(l[2], l[3]);
    }
}

// ===========================================================================
// fp16 2-term tensor-core GEMM: C = (Ah+Al)@Wh^T + bias.
// CTA 128x128, BK=32, 256 threads (8 warps, 64x32 warp tiles), cp.async x2.
// Output modes: fp32 Cout, or fp16 outh (+outl if non-null).
// ===========================================================================
#define SSTR 40
#define KTILE (128*SSTR)
#define STAGE_ELEMS (3*KTILE)           // Ah, Al, Wh
#define GEMM_SMEM (2*STAGE_ELEMS*2)     // 61440 bytes

__global__ __launch_bounds__(256, 2) void gemm_pre_kernel(
    const __half* __restrict__ Ah_g, const __half* __restrict__ Al_g,
    const __half* __restrict__ Wh_g,
    const float* __restrict__ bias, float* __restrict__ Cout,
    __half* __restrict__ outh, __half* __restrict__ outl)
{
    extern __shared__ __half smem[];

    const int tid  = threadIdx.x;
    const int wid  = tid >> 5;
    const int lane = tid & 31;
    const int g    = lane >> 2;
    const int t4   = lane & 3;
    const int m0   = blockIdx.y * 128;
    const int n0   = blockIdx.x * 128;
    const int wm   = (wid & 1) * 64;
    const int wn   = (wid >> 1) * 32;

    const __half* srcs[3] = {Ah_g, Al_g, Wh_g};

    float acc[4][4][4];
#pragma unroll
    for (int i = 0; i < 4; i++)
#pragma unroll
        for (int j = 0; j < 4; j++)
#pragma unroll
            for (int r = 0; r < 4; r++) acc[i][j][r] = 0.f;

    auto issue_stage = [&](int kt, int s) {
        const int kk = kt * 32;
#pragma unroll
        for (int p = 0; p < 6; p++) {
            int idx  = tid + 256*p;          // 0..1535
            int tile = idx >> 9;             // 0..2
            int rem  = idx & 511;
            int r    = rem >> 2;             // 0..127
            int c    = rem & 3;              // 16B chunks
            int grow = ((tile < 2) ? m0 : n0) + r;
            const __half* src = srcs[tile] + (size_t)grow * GK + kk + c*8;
            __half* dst = smem + s*STAGE_ELEMS + tile*KTILE + r*SSTR + c*8;
            unsigned int daddr = (unsigned int)__cvta_generic_to_shared(dst);
            asm volatile("cp.async.cg.shared.global [%0], [%1], 16;\n"
                         :: "r"(daddr), "l"(src));
        }
        asm volatile("cp.async.commit_group;\n");
    };

    issue_stage(0, 0);

    const int nk = GK / 32;
    for (int kt = 0; kt < nk; kt++) {
        const int s = kt & 1;
        const bool more = (kt + 1 < nk);
        if (more) {
            issue_stage(kt + 1, s ^ 1);
            asm volatile("cp.async.wait_group 1;\n");
        } else {
            asm volatile("cp.async.wait_group 0;\n");
        }
        __syncthreads();

        const __half* sAh = smem + s*STAGE_ELEMS;
        const __half* sAl = sAh + KTILE;
        const __half* sWh = sAh + 2*KTILE;

#pragma unroll
        for (int ks = 0; ks < 32; ks += 16) {
            unsigned int ah[4][4], al[4][4], bh[4][2];
#pragma unroll
            for (int i = 0; i < 4; i++) {
                ldsm4(sAh, wm + i*16, ks, lane, SSTR, ah[i]);
                ldsm4(sAl, wm + i*16, ks, lane, SSTR, al[i]);
            }
#pragma unroll
            for (int j = 0; j < 4; j++)
                ldsm2(sWh, wn + j*8, ks, lane, SSTR, bh[j]);
#pragma unroll
            for (int i = 0; i < 4; i++)
#pragma unroll
                for (int j = 0; j < 4; j++) {
                    mma_fp16(acc[i][j], ah[i], bh[j]);
                    mma_fp16(acc[i][j], al[i], bh[j]);
                }
        }
        __syncthreads();
    }

    // epilogue
#pragma unroll
    for (int i = 0; i < 4; i++)
#pragma unroll
        for (int j = 0; j < 4; j++) {
            const int r = m0 + wm + i*16 + g;
            const int c = n0 + wn + j*8 + t4*2;
            const float b0v = bias[c], b1v = bias[c+1];
            float v00 = acc[i][j][0] + b0v, v01 = acc[i][j][1] + b1v;
            float v10 = acc[i][j][2] + b0v, v11 = acc[i][j][3] + b1v;
            if (Cout) {
                float2 w0 = {v00, v01}, w1 = {v10, v11};
                *(float2*)&Cout[(size_t)r       * CCH + c] = w0;
                *(float2*)&Cout[(size_t)(r + 8) * CCH + c] = w1;
            } else {
                __half h0,l0,h1,l1,h2,l2,h3,l3;
                split_fp16(v00, h0, l0); split_fp16(v01, h1, l1);
                split_fp16(v10, h2, l2); split_fp16(v11, h3, l3);
                *(__half2*)&outh[(size_t)r      *CCH + c] = __halves2half2(h0, h1);
                *(__half2*)&outh[(size_t)(r + 8)*CCH + c] = __halves2half2(h2, h3);
                if (outl) {
                    *(__half2*)&outl[(size_t)r      *CCH + c] = __halves2half2(l0, l1);
                    *(__half2*)&outl[(size_t)(r + 8)*CCH + c] = __halves2half2(l2, l3);
                }
            }
        }
}

// ===========================================================================
// fp16 flash attention: S = 3-term (exact), PV = 1-term (P,V single fp16).
// CTA: 64 queries x one (b,h), 4 warps (R6 best-measured config).
// Smem: Qh,Ql,Kh,Kl row-major [r][d]; Vh [t][d]. 5 tiles, 46 KB.
// ===========================================================================
#define ASTR 72
#define ATILE (64*ASTR)
#define ATTN_SMEM (5*ATILE*2)     // 46080 bytes

__global__ __launch_bounds__(128) void attn_mma_kernel(
    const __half* __restrict__ qkh, const __half* __restrict__ qkl,
    const __half* __restrict__ vgh,
    __half* __restrict__ yh, __half* __restrict__ yl)
{
    extern __shared__ __half smA[];
    __half* Qh = smA;
    __half* Ql = smA +   ATILE;
    __half* Kh = smA + 2*ATILE;
    __half* Kl = smA + 3*ATILE;
    __half* Vh = smA + 4*ATILE;   // [t][d]

    const int tid  = threadIdx.x;
    const int wid  = tid >> 5;
    const int lane = tid & 31;
    const int g    = lane >> 2;
    const int t4   = lane & 3;
    const int qi = blockIdx.x;
    const int bh = blockIdx.y;
    const int b  = bh / HH, h = bh % HH;
    const int q0 = qi * 64;
    const size_t base = ((size_t)b * TT) * CCH + (size_t)h * DD;

    // ---- load Q tile ----
#pragma unroll
    for (int p = 0; p < 4; p++) {
        int idx = tid + 128*p;           // 0..511
        int r   = idx >> 3;              // 0..63
        int c8  = (idx & 7) * 8;         // 0..56
        size_t gg = base + (size_t)(q0 + r)*CCH + c8;
        *(uint4*)&Qh[r*ASTR + c8] = *(const uint4*)&qkh[gg];
        *(uint4*)&Ql[r*ASTR + c8] = *(const uint4*)&qkl[gg];
    }

    float m0r = -1e30f, m1r = -1e30f, l0r = 0.f, l1r = 0.f;
    float o[8][4];
#pragma unroll
    for (int j = 0; j < 8; j++)
#pragma unroll
        for (int r = 0; r < 4; r++) o[j][r] = 0.f;

    for (int kv = 0; kv <= qi; kv++) {
        __syncthreads();   // prior-iter readers done (first iter covers Q fill)
#pragma unroll
        for (int p = 0; p < 4; p++) {
            int idx = tid + 128*p;
            int r   = idx >> 3;
            int c8  = (idx & 7) * 8;
            size_t gg = base + (size_t)(kv*64 + r)*CCH + c8;
            *(uint4*)&Kh[r*ASTR + c8] = *(const uint4*)&qkh[gg];
            *(uint4*)&Kl[r*ASTR + c8] = *(const uint4*)&qkl[gg];
            *(uint4*)&Vh[r*ASTR + c8] = *(const uint4*)&vgh[gg];
        }
        __syncthreads();

        // ---- S = Q @ K^T (3-term, exact) ----
        float s[8][4];
#pragma unroll
        for (int j = 0; j < 8; j++)
#pragma unroll
            for (int r = 0; r < 4; r++) s[j][r] = 0.f;

#pragma unroll
        for (int ks = 0; ks < 4; ks++) {
            unsigned int ah[4], al[4];
            ldsm4(Qh, wid*16, ks*16, lane, ASTR, ah);
            ldsm4(Ql, wid*16, ks*16, lane, ASTR, al);
#pragma unroll
            for (int j = 0; j < 8; j++) {
                unsigned int kbh[2], kbl[2];
                ldsm2(Kh, j*8, ks*16, lane, ASTR, kbh);
                ldsm2(Kl, j*8, ks*16, lane, ASTR, kbl);
                mma_fp16(s[j], ah, kbh);
                mma_fp16(s[j], ah, kbl);
                mma_fp16(s[j], al, kbh);
            }
        }

        // ---- scale + causal mask ----
        const float scale = 0.125f;
        const int row0 = wid*16 + g;
        const int row1 = row0 + 8;
        if (kv == qi) {
#pragma unroll
            for (int j = 0; j < 8; j++) {
                const int c0 = j*8 + 2*t4, c1 = c0 + 1;
                s[j][0] = (c0 > row0) ? -1e30f : s[j][0]*scale;
                s[j][1] = (c1 > row0) ? -1e30f : s[j][1]*scale;
                s[j][2] = (c0 > row1) ? -1e30f : s[j][2]*scale;
                s[j][3] = (c1 > row1) ? -1e30f : s[j][3]*scale;
            }
        } else {
#pragma unroll
            for (int j = 0; j < 8; j++)
#pragma unroll
                for (int r = 0; r < 4; r++) s[j][r] *= scale;
        }

        // ---- online softmax (quad reductions) ----
        float mx0 = -1e30f, mx1 = -1e30f;
#pragma unroll
        for (int j = 0; j < 8; j++) {
            mx0 = fmaxf(mx0, fmaxf(s[j][0], s[j][1]));
            mx1 = fmaxf(mx1, fmaxf(s[j][2], s[j][3]));
        }
        mx0 = fmaxf(mx0, __shfl_xor_sync(0xffffffffu, mx0, 1));
        mx0 = fmaxf(mx0, __shfl_xor_sync(0xffffffffu, mx0, 2));
        mx1 = fmaxf(mx1, __shfl_xor_sync(0xffffffffu, mx1, 1));
        mx1 = fmaxf(mx1, __shfl_xor_sync(0xffffffffu, mx1, 2));

        const float mn0 = fmaxf(m0r, mx0), mn1 = fmaxf(m1r, mx1);
        const float cr0 = __expf(m0r - mn0), cr1 = __expf(m1r - mn1);
        m0r = mn0; m1r = mn1;

        float sum0 = 0.f, sum1 = 0.f;
#pragma unroll
        for (int j = 0; j < 8; j++) {
            s[j][0] = __expf(s[j][0] - mn0);
            s[j][1] = __expf(s[j][1] - mn0);
            s[j][2] = __expf(s[j][2] - mn1);
            s[j][3] = __expf(s[j][3] - mn1);
            sum0 += s[j][0] + s[j][1];
            sum1 += s[j][2] + s[j][3];
        }
        sum0 += __shfl_xor_sync(0xffffffffu, sum0, 1);
        sum0 += __shfl_xor_sync(0xffffffffu, sum0, 2);
        sum1 += __shfl_xor_sync(0xffffffffu, sum1, 1);
        sum1 += __shfl_xor_sync(0xffffffffu, sum1, 2);
        l0r = l0r*cr0 + sum0;
        l1r = l1r*cr1 + sum1;

#pragma unroll
        for (int j = 0; j < 8; j++) {
            o[j][0] *= cr0; o[j][1] *= cr0;
            o[j][2] *= cr1; o[j][3] *= cr1;
        }

        // ---- O += P @ V (1-term: P, V single fp16) ----
#pragma unroll
        for (int c = 0; c < 4; c++) {
            unsigned int aPh[4];
#pragma unroll
            for (int half = 0; half < 2; half++) {   // tiles 2c, 2c+1
                const int jt = 2*c + half;
                __half p0 = __float2half_rn(s[jt][0]);
                __half p1 = __float2half_rn(s[jt][1]);
                __half p2 = __float2half_rn(s[jt][2]);
                __half p3 = __float2half_rn(s[jt][3]);
                __half2 P01 = __halves2half2(p0, p1);
                __half2 P23 = __halves2half2(p2, p3);
                aPh[2*half    ] = *(unsigned int*)&P01;
                aPh[2*half + 1] = *(unsigned int*)&P23;
            }
#pragma unroll
            for (int j = 0; j < 8; j++) {
                unsigned int vbh[2];
                ldsm2t(Vh, c*16, j*8, lane, ASTR, vbh);
                mma_fp16(o[j], aPh, vbh);
            }
        }
    }

    // ---- normalize + write y as fp16 hi/lo ----
    const float inv0 = 1.f / l0r, inv1 = 1.f / l1r;
    const int r0 = q0 + wid*16 + g;
    const int r1 = r0 + 8;
#pragma unroll
    for (int j = 0; j < 8; j++) {
        const int c = j*8 + 2*t4;
        float v00 = o[j][0]*inv0, v01 = o[j][1]*inv0;
        float v10 = o[j][2]*inv1, v11 = o[j][3]*inv1;
        __half h0,l0,h1,l1,h2,l2,h3,l3;
        split_fp16(v00, h0, l0); split_fp16(v01, h1, l1);
        split_fp16(v10, h2, l2); split_fp16(v11, h3, l3);
        *(__half2*)&yh[base + (size_t)r0*CCH + c] = __halves2half2(h0, h1);
        *(__half2*)&yh[base + (size_t)r1*CCH + c] = __halves2half2(h2, h3);
        *(__half2*)&yl[base + (size_t)r0*CCH + c] = __halves2half2(l0, l1);
        *(__half2*)&yl[base + (size_t)r1*CCH + c] = __halves2half2(l2, l3);
    }
}

// ---------------------------------------------------------------------------
extern "C" void kernel_launch(void* const* d_in, const int* in_sizes, int n_in,
                              void* d_out, int out_size)
{
    const float* hs  = (const float*)d_in[0];
    const float* Wqk = (const float*)d_in[1];
    const float* bqk = (const float*)d_in[2];
    const float* Wv  = (const float*)d_in[3];
    const float* bv  = (const float*)d_in[4];
    const float* Wo  = (const float*)d_in[5];
    const float* bo  = (const float*)d_in[6];
    float* out = (float*)d_out;

    __half *hs_h,*hs_l,*wqk_h,*wv_h,*wo_h;
    __half *qk_h,*qk_l,*v_h,*y_h,*y_l;
    cudaGetSymbolAddress((void**)&hs_h, g_hs_h);   cudaGetSymbolAddress((void**)&hs_l, g_hs_l);
    cudaGetSymbolAddress((void**)&wqk_h, g_Wqk_h);
    cudaGetSymbolAddress((void**)&wv_h, g_Wv_h);
    cudaGetSymbolAddress((void**)&wo_h, g_Wo_h);
    cudaGetSymbolAddress((void**)&qk_h, g_qk_h);   cudaGetSymbolAddress((void**)&qk_l, g_qk_l);
    cudaGetSymbolAddress((void**)&v_h, g_v_h);
    cudaGetSymbolAddress((void**)&y_h, g_y_h);     cudaGetSymbolAddress((void**)&y_l, g_y_l);

    cudaFuncSetAttribute(attn_mma_kernel,
                         cudaFuncAttributeMaxDynamicSharedMemorySize, ATTN_SMEM);
    cudaFuncSetAttribute(gemm_pre_kernel,
                         cudaFuncAttributeMaxDynamicSharedMemorySize, GEMM_SMEM);

    // fused pre-split: hs -> h,l ; weights -> h only
    split4_kernel<<<(N4_TOT+255)/256, 256>>>(
        (const float4*)hs, (const float4*)Wqk, (const float4*)Wv, (const float4*)Wo,
        (__half2*)hs_h, (__half2*)hs_l,
        (__half2*)wqk_h, (__half2*)wv_h, (__half2*)wo_h);

    dim3 ggrid(CCH/128, MTOK/128);   // (8, 32)
    gemm_pre_kernel<<<ggrid, 256, GEMM_SMEM>>>(hs_h, hs_l, wqk_h,
        bqk, nullptr, qk_h, qk_l);
    gemm_pre_kernel<<<ggrid, 256, GEMM_SMEM>>>(hs_h, hs_l, wv_h,
        bv, nullptr, v_h, nullptr);

    attn_mma_kernel<<<dim3(TT/64, BB*HH), 128, ATTN_SMEM>>>(qk_h, qk_l,
        v_h, y_h, y_l);

    gemm_pre_kernel<<<ggrid, 256, GEMM_SMEM>>>(y_h, y_l, wo_h,
        bo, out, nullptr, nullptr);
}

// round 12
// speedup vs baseline: 1.8481x; 1.2636x over previous
#include <cuda_runtime.h>
#include <cuda_fp16.h>
#include <cstdint>

#define BB 2
#define TT 2048
#define CCH 1024
#define HH 16
#define DD 64
#define MTOK (BB*TT)          // 4096 tokens
#define GK   1024

// ---------------------------------------------------------------------------
// Scratch (allocation-free rule: __device__ globals), fp16
// ---------------------------------------------------------------------------
__device__ __half g_hs_h[MTOK*CCH],  g_hs_l[MTOK*CCH];
__device__ __half g_Wqk_h[CCH*CCH];
__device__ __half g_Wv_h [CCH*CCH];
__device__ __half g_Wo_h [CCH*CCH];
__device__ __half g_qk_h[MTOK*CCH];
__device__ __half g_v_h [MTOK*CCH];
__device__ __half g_y_h [MTOK*CCH], g_y_l [MTOK*CCH];

// ===========================================================================
// Helpers
// ===========================================================================
__device__ __forceinline__ void split_fp16(float x, __half& h, __half& l)
{
    h = __float2half_rn(x);
    l = __float2half_rn(x - __half2float(h));
}

__device__ __forceinline__ void mma_fp16(float c[4],
    const unsigned int a[4], const unsigned int b[2])
{
    asm volatile(
        "mma.sync.aligned.m16n8k16.row.col.f32.f16.f16.f32 "
        "{%0,%1,%2,%3}, {%4,%5,%6,%7}, {%8,%9}, {%0,%1,%2,%3};"
        : "+f"(c[0]), "+f"(c[1]), "+f"(c[2]), "+f"(c[3])
        : "r"(a[0]), "r"(a[1]), "r"(a[2]), "r"(a[3]), "r"(b[0]), "r"(b[1]));
}

__device__ __forceinline__ void ldsm4(const __half* base, int row0,
    int kc, int lane, int stride, unsigned int r[4])
{
    const __half* p = base + (row0 + (lane & 15)) * stride
                           + kc + ((lane >> 4) << 3);
    unsigned int addr = (unsigned int)__cvta_generic_to_shared(p);
    asm volatile("ldmatrix.sync.aligned.m8n8.x4.shared.b16 {%0,%1,%2,%3}, [%4];"
        : "=r"(r[0]), "=r"(r[1]), "=r"(r[2]), "=r"(r[3]) : "r"(addr));
}

__device__ __forceinline__ void ldsm2(const __half* base, int row0,
    int kc, int lane, int stride, unsigned int r[2])
{
    const __half* p = base + (row0 + (lane & 7)) * stride
                           + kc + (((lane >> 3) & 1) << 3);
    unsigned int addr = (unsigned int)__cvta_generic_to_shared(p);
    asm volatile("ldmatrix.sync.aligned.m8n8.x2.shared.b16 {%0,%1}, [%2];"
        : "=r"(r[0]), "=r"(r[1]) : "r"(addr));
}

// transposed B-fragment load: smem tile is [k][n] row-major (rows = k)
__device__ __forceinline__ void ldsm2t(const __half* base, int k0,
    int n0, int lane, int stride, unsigned int r[2])
{
    const __half* p = base
        + (k0 + (lane & 7) + ((lane >> 3) & 1) * 8) * stride + n0;
    unsigned int addr = (unsigned int)__cvta_generic_to_shared(p);
    asm volatile("ldmatrix.sync.aligned.m8n8.x2.trans.shared.b16 {%0,%1}, [%2];"
        : "=r"(r[0]), "=r"(r[1]) : "r"(addr));
}

// ===========================================================================
// Fused split: hs -> (h,l); weights -> h only
// ===========================================================================
#define N4_HS (MTOK*CCH/4)
#define N4_W  (CCH*CCH/4)
#define N4_TOT (N4_HS + 3*N4_W)

__global__ void split4_kernel(
    const float4* __restrict__ hs, const float4* __restrict__ wqk,
    const float4* __restrict__ wv, const float4* __restrict__ wo,
    __half2* __restrict__ hs_h, __half2* __restrict__ hs_l,
    __half2* __restrict__ wqk_h, __half2* __restrict__ wv_h,
    __half2* __restrict__ wo_h)
{
    int i = blockIdx.x * blockDim.x + threadIdx.x;
    if (i >= N4_TOT) return;
    const float4* src; __half2 *dh, *dl; int off;
    if (i < N4_HS)            { src = hs;  dh = hs_h;  dl = hs_l;  off = i; }
    else if (i < N4_HS+N4_W)  { src = wqk; dh = wqk_h; dl = nullptr; off = i - N4_HS; }
    else if (i < N4_HS+2*N4_W){ src = wv;  dh = wv_h;  dl = nullptr; off = i - N4_HS - N4_W; }
    else                      { src = wo;  dh = wo_h;  dl = nullptr; off = i - N4_HS - 2*N4_W; }
    float4 v = src[off];
    float f[4] = {v.x, v.y, v.z, v.w};
    __half h[4], l[4];
#pragma unroll
    for (int q = 0; q < 4; q++) split_fp16(f[q], h[q], l[q]);
    dh[2*off    ] = __halves2half2(h[0], h[1]);
    dh[2*off + 1] = __halves2half2(h[2], h[3]);
    if (dl) {
        dl[2*off    ] = __halves2half2(l[0], l[1]);
        dl[2*off + 1] = __halves2half2(l[2], l[3]);
    }
}

// ===========================================================================
// fp16 tensor-core GEMM, templated on A exactness.
//   EXACT_A: C = (Ah+Al)@Wh^T + bias  (2 mma/k16)
//   else:    C = Ah@Wh^T + bias       (1 mma/k16)
// CTA 128x128, BK=32, 256 threads (8 warps, 64x32 warp tiles), cp.async x2.
// ===========================================================================
#define SSTR 40
#define KTILE (128*SSTR)
#define STAGE3 (3*KTILE)
#define GEMM_SMEM (2*STAGE3*2)     // 61440 bytes (worst case)

template<bool EXACT_A>
__global__ __launch_bounds__(256, 2) void gemm_pre_kernel(
    const __half* __restrict__ Ah_g, const __half* __restrict__ Al_g,
    const __half* __restrict__ Wh_g,
    const float* __restrict__ bias, float* __restrict__ Cout,
    __half* __restrict__ outh, __half* __restrict__ outl)
{
    extern __shared__ __half smem[];

    const int NT = EXACT_A ? 3 : 2;          // tiles per stage
    const int STAGE_ELEMS = NT * KTILE;

    const int tid  = threadIdx.x;
    const int wid  = tid >> 5;
    const int lane = tid & 31;
    const int g    = lane >> 2;
    const int t4   = lane & 3;
    const int m0   = blockIdx.y * 128;
    const int n0   = blockIdx.x * 128;
    const int wm   = (wid & 1) * 64;
    const int wn   = (wid >> 1) * 32;

    float acc[4][4][4];
#pragma unroll
    for (int i = 0; i < 4; i++)
#pragma unroll
        for (int j = 0; j < 4; j++)
#pragma unroll
            for (int r = 0; r < 4; r++) acc[i][j][r] = 0.f;

    auto issue_stage = [&](int kt, int s) {
        const int kk = kt * 32;
#pragma unroll
        for (int p = 0; p < 2*NT; p++) {
            int idx  = tid + 256*p;          // 0..NT*512-1
            int tile = idx >> 9;             // 0..NT-1
            int rem  = idx & 511;
            int r    = rem >> 2;             // 0..127
            int c    = rem & 3;              // 16B chunks
            const __half* sb = (tile == 0) ? Ah_g
                             : (EXACT_A && tile == 1) ? Al_g : Wh_g;
            int grow = ((tile < NT-1) ? m0 : n0) + r;
            const __half* src = sb + (size_t)grow * GK + kk + c*8;
            __half* dst = smem + s*STAGE_ELEMS + tile*KTILE + r*SSTR + c*8;
            unsigned int daddr = (unsigned int)__cvta_generic_to_shared(dst);
            asm volatile("cp.async.cg.shared.global [%0], [%1], 16;\n"
                         :: "r"(daddr), "l"(src));
        }
        asm volatile("cp.async.commit_group;\n");
    };

    issue_stage(0, 0);

    const int nk = GK / 32;
    for (int kt = 0; kt < nk; kt++) {
        const int s = kt & 1;
        const bool more = (kt + 1 < nk);
        if (more) {
            issue_stage(kt + 1, s ^ 1);
            asm volatile("cp.async.wait_group 1;\n");
        } else {
            asm volatile("cp.async.wait_group 0;\n");
        }
        __syncthreads();

        const __half* sAh = smem + s*STAGE_ELEMS;
        const __half* sAl = sAh + KTILE;                  // valid iff EXACT_A
        const __half* sWh = sAh + (NT-1)*KTILE;

#pragma unroll
        for (int ks = 0; ks < 32; ks += 16) {
            unsigned int ah[4][4], al[4][4], bh[4][2];
#pragma unroll
            for (int i = 0; i < 4; i++) {
                ldsm4(sAh, wm + i*16, ks, lane, SSTR, ah[i]);
                if (EXACT_A)
                    ldsm4(sAl, wm + i*16, ks, lane, SSTR, al[i]);
            }
#pragma unroll
            for (int j = 0; j < 4; j++)
                ldsm2(sWh, wn + j*8, ks, lane, SSTR, bh[j]);
#pragma unroll
            for (int i = 0; i < 4; i++)
#pragma unroll
                for (int j = 0; j < 4; j++) {
                    mma_fp16(acc[i][j], ah[i], bh[j]);
                    if (EXACT_A)
                        mma_fp16(acc[i][j], al[i], bh[j]);
                }
        }
        __syncthreads();
    }

    // epilogue
#pragma unroll
    for (int i = 0; i < 4; i++)
#pragma unroll
        for (int j = 0; j < 4; j++) {
            const int r = m0 + wm + i*16 + g;
            const int c = n0 + wn + j*8 + t4*2;
            const float b0v = bias[c], b1v = bias[c+1];
            float v00 = acc[i][j][0] + b0v, v01 = acc[i][j][1] + b1v;
            float v10 = acc[i][j][2] + b0v, v11 = acc[i][j][3] + b1v;
            if (Cout) {
                float2 w0 = {v00, v01}, w1 = {v10, v11};
                *(float2*)&Cout[(size_t)r       * CCH + c] = w0;
                *(float2*)&Cout[(size_t)(r + 8) * CCH + c] = w1;
            } else {
                __half h0,l0,h1,l1,h2,l2,h3,l3;
                split_fp16(v00, h0, l0); split_fp16(v01, h1, l1);
                split_fp16(v10, h2, l2); split_fp16(v11, h3, l3);
                *(__half2*)&outh[(size_t)r      *CCH + c] = __halves2half2(h0, h1);
                *(__half2*)&outh[(size_t)(r + 8)*CCH + c] = __halves2half2(h2, h3);
                if (outl) {
                    *(__half2*)&outl[(size_t)r      *CCH + c] = __halves2half2(l0, l1);
                    *(__half2*)&outl[(size_t)(r + 8)*CCH + c] = __halves2half2(l2, l3);
                }
            }
        }
}

// ===========================================================================
// fp16 flash attention, minimal-mma: S = Qh@Kh^T (1 mma), PV = 1 mma.
// CTA: 64 queries x one (b,h), 4 warps. Smem: Qh,Kh,Vh = 27 KB.
// ===========================================================================
#define ASTR 72
#define ATILE (64*ASTR)
#define ATTN_SMEM (3*ATILE*2)     // 27648 bytes

__global__ __launch_bounds__(128) void attn_mma_kernel(
    const __half* __restrict__ qkh, const __half* __restrict__ vgh,
    __half* __restrict__ yh, __half* __restrict__ yl)
{
    extern __shared__ __half smA[];
    __half* Qh = smA;
    __half* Kh = smA +   ATILE;
    __half* Vh = smA + 2*ATILE;   // [t][d]

    const int tid  = threadIdx.x;
    const int wid  = tid >> 5;
    const int lane = tid & 31;
    const int g    = lane >> 2;
    const int t4   = lane & 3;
    const int qi = blockIdx.x;
    const int bh = blockIdx.y;
    const int b  = bh / HH, h = bh % HH;
    const int q0 = qi * 64;
    const size_t base = ((size_t)b * TT) * CCH + (size_t)h * DD;

    // ---- load Q tile ----
#pragma unroll
    for (int p = 0; p < 4; p++) {
        int idx = tid + 128*p;           // 0..511
        int r   = idx >> 3;              // 0..63
        int c8  = (idx & 7) * 8;         // 0..56
        size_t gg = base + (size_t)(q0 + r)*CCH + c8;
        *(uint4*)&Qh[r*ASTR + c8] = *(const uint4*)&qkh[gg];
    }

    float m0r = -1e30f, m1r = -1e30f, l0r = 0.f, l1r = 0.f;
    float o[8][4];
#pragma unroll
    for (int j = 0; j < 8; j++)
#pragma unroll
        for (int r = 0; r < 4; r++) o[j][r] = 0.f;

    for (int kv = 0; kv <= qi; kv++) {
        __syncthreads();   // prior-iter readers done (first iter covers Q fill)
#pragma unroll
        for (int p = 0; p < 8; p++) {
            int idx  = tid + 128*p;          // 0..1023
            int tile = idx >> 9;             // 0: K, 1: V
            int rem  = idx & 511;
            int r    = rem >> 3;
            int c8   = (rem & 7) * 8;
            size_t gg = base + (size_t)(kv*64 + r)*CCH + c8;
            __half* dst = tile ? Vh : Kh;
            const __half* src = tile ? vgh : qkh;
            *(uint4*)&dst[r*ASTR + c8] = *(const uint4*)&src[gg];
        }
        __syncthreads();

        // ---- S = Qh @ Kh^T (1 mma per tile) ----
        float s[8][4];
#pragma unroll
        for (int j = 0; j < 8; j++)
#pragma unroll
            for (int r = 0; r < 4; r++) s[j][r] = 0.f;

#pragma unroll
        for (int ks = 0; ks < 4; ks++) {
            unsigned int ah[4];
            ldsm4(Qh, wid*16, ks*16, lane, ASTR, ah);
#pragma unroll
            for (int j = 0; j < 8; j++) {
                unsigned int kbh[2];
                ldsm2(Kh, j*8, ks*16, lane, ASTR, kbh);
                mma_fp16(s[j], ah, kbh);
            }
        }

        // ---- scale + causal mask ----
        const float scale = 0.125f;
        const int row0 = wid*16 + g;
        const int row1 = row0 + 8;
        if (kv == qi) {
#pragma unroll
            for (int j = 0; j < 8; j++) {
                const int c0 = j*8 + 2*t4, c1 = c0 + 1;
                s[j][0] = (c0 > row0) ? -1e30f : s[j][0]*scale;
                s[j][1] = (c1 > row0) ? -1e30f : s[j][1]*scale;
                s[j][2] = (c0 > row1) ? -1e30f : s[j][2]*scale;
                s[j][3] = (c1 > row1) ? -1e30f : s[j][3]*scale;
            }
        } else {
#pragma unroll
            for (int j = 0; j < 8; j++)
#pragma unroll
                for (int r = 0; r < 4; r++) s[j][r] *= scale;
        }

        // ---- online softmax (quad reductions) ----
        float mx0 = -1e30f, mx1 = -1e30f;
#pragma unroll
        for (int j = 0; j < 8; j++) {
            mx0 = fmaxf(mx0, fmaxf(s[j][0], s[j][1]));
            mx1 = fmaxf(mx1, fmaxf(s[j][2], s[j][3]));
        }
        mx0 = fmaxf(mx0, __shfl_xor_sync(0xffffffffu, mx0, 1));
        mx0 = fmaxf(mx0, __shfl_xor_sync(0xffffffffu, mx0, 2));
        mx1 = fmaxf(mx1, __shfl_xor_sync(0xffffffffu, mx1, 1));
        mx1 = fmaxf(mx1, __shfl_xor_sync(0xffffffffu, mx1, 2));

        const float mn0 = fmaxf(m0r, mx0), mn1 = fmaxf(m1r, mx1);
        const float cr0 = __expf(m0r - mn0), cr1 = __expf(m1r - mn1);
        m0r = mn0; m1r = mn1;

        float sum0 = 0.f, sum1 = 0.f;
#pragma unroll
        for (int j = 0; j < 8; j++) {
            s[j][0] = __expf(s[j][0] - mn0);
            s[j][1] = __expf(s[j][1] - mn0);
            s[j][2] = __expf(s[j][2] - mn1);
            s[j][3] = __expf(s[j][3] - mn1);
            sum0 += s[j][0] + s[j][1];
            sum1 += s[j][2] + s[j][3];
        }
        sum0 += __shfl_xor_sync(0xffffffffu, sum0, 1);
        sum0 += __shfl_xor_sync(0xffffffffu, sum0, 2);
        sum1 += __shfl_xor_sync(0xffffffffu, sum1, 1);
        sum1 += __shfl_xor_sync(0xffffffffu, sum1, 2);
        l0r = l0r*cr0 + sum0;
        l1r = l1r*cr1 + sum1;

#pragma unroll
        for (int j = 0; j < 8; j++) {
            o[j][0] *= cr0; o[j][1] *= cr0;
            o[j][2] *= cr1; o[j][3] *= cr1;
        }

        // ---- O += P @ V (1 mma) ----
#pragma unroll
        for (int c = 0; c < 4; c++) {
            unsigned int aPh[4];
#pragma unroll
            for (int half = 0; half < 2; half++) {
                const int jt = 2*c + half;
                __half p0 = __float2half_rn(s[jt][0]);
                __half p1 = __float2half_rn(s[jt][1]);
                __half p2 = __float2half_rn(s[jt][2]);
                __half p3 = __float2half_rn(s[jt][3]);
                __half2 P01 = __halves2half2(p0, p1);
                __half2 P23 = __halves2half2(p2, p3);
                aPh[2*half    ] = *(unsigned int*)&P01;
                aPh[2*half + 1] = *(unsigned int*)&P23;
            }
#pragma unroll
            for (int j = 0; j < 8; j++) {
                unsigned int vbh[2];
                ldsm2t(Vh, c*16, j*8, lane, ASTR, vbh);
                mma_fp16(o[j], aPh, vbh);
            }
        }
    }

    // ---- normalize + write y as fp16 hi/lo ----
    const float inv0 = 1.f / l0r, inv1 = 1.f / l1r;
    const int r0 = q0 + wid*16 + g;
    const int r1 = r0 + 8;
#pragma unroll
    for (int j = 0; j < 8; j++) {
        const int c = j*8 + 2*t4;
        float v00 = o[j][0]*inv0, v01 = o[j][1]*inv0;
        float v10 = o[j][2]*inv1, v11 = o[j][3]*inv1;
        __half h0,l0,h1,l1,h2,l2,h3,l3;
        split_fp16(v00, h0, l0); split_fp16(v01, h1, l1);
        split_fp16(v10, h2, l2); split_fp16(v11, h3, l3);
        *(__half2*)&yh[base + (size_t)r0*CCH + c] = __halves2half2(h0, h1);
        *(__half2*)&yh[base + (size_t)r1*CCH + c] = __halves2half2(h2, h3);
        *(__half2*)&yl[base + (size_t)r0*CCH + c] = __halves2half2(l0, l1);
        *(__half2*)&yl[base + (size_t)r1*CCH + c] = __halves2half2(l2, l3);
    }
}

// ---------------------------------------------------------------------------
extern "C" void kernel_launch(void* const* d_in, const int* in_sizes, int n_in,
                              void* d_out, int out_size)
{
    const float* hs  = (const float*)d_in[0];
    const float* Wqk = (const float*)d_in[1];
    const float* bqk = (const float*)d_in[2];
    const float* Wv  = (const float*)d_in[3];
    const float* bv  = (const float*)d_in[4];
    const float* Wo  = (const float*)d_in[5];
    const float* bo  = (const float*)d_in[6];
    float* out = (float*)d_out;

    __half *hs_h,*hs_l,*wqk_h,*wv_h,*wo_h;
    __half *qk_h,*v_h,*y_h,*y_l;
    cudaGetSymbolAddress((void**)&hs_h, g_hs_h);   cudaGetSymbolAddress((void**)&hs_l, g_hs_l);
    cudaGetSymbolAddress((void**)&wqk_h, g_Wqk_h);
    cudaGetSymbolAddress((void**)&wv_h, g_Wv_h);
    cudaGetSymbolAddress((void**)&wo_h, g_Wo_h);
    cudaGetSymbolAddress((void**)&qk_h, g_qk_h);
    cudaGetSymbolAddress((void**)&v_h, g_v_h);
    cudaGetSymbolAddress((void**)&y_h, g_y_h);     cudaGetSymbolAddress((void**)&y_l, g_y_l);

    cudaFuncSetAttribute(attn_mma_kernel,
                         cudaFuncAttributeMaxDynamicSharedMemorySize, ATTN_SMEM);
    cudaFuncSetAttribute(gemm_pre_kernel<true>,
                         cudaFuncAttributeMaxDynamicSharedMemorySize, GEMM_SMEM);
    cudaFuncSetAttribute(gemm_pre_kernel<false>,
                         cudaFuncAttributeMaxDynamicSharedMemorySize, GEMM_SMEM);

    // fused pre-split: hs -> h,l ; weights -> h only
    split4_kernel<<<(N4_TOT+255)/256, 256>>>(
        (const float4*)hs, (const float4*)Wqk, (const float4*)Wv, (const float4*)Wo,
        (__half2*)hs_h, (__half2*)hs_l,
        (__half2*)wqk_h, (__half2*)wv_h, (__half2*)wo_h);

    dim3 ggrid(CCH/128, MTOK/128);   // (8, 32)
    // qk projection: 1-term (logit-damped error), h output only
    gemm_pre_kernel<false><<<ggrid, 256, GEMM_SMEM>>>(hs_h, nullptr, wqk_h,
        bqk, nullptr, qk_h, nullptr);
    // v projection: 2-term (direct output error)
    gemm_pre_kernel<true><<<ggrid, 256, GEMM_SMEM>>>(hs_h, hs_l, wv_h,
        bv, nullptr, v_h, nullptr);

    attn_mma_kernel<<<dim3(TT/64, BB*HH), 128, ATTN_SMEM>>>(qk_h, v_h, y_h, y_l);

    // output projection: 2-term (y exact)
    gemm_pre_kernel<true><<<ggrid, 256, GEMM_SMEM>>>(y_h, y_l, wo_h,
        bo, out, nullptr, nullptr);
}

// round 13
// speedup vs baseline: 2.3930x; 1.2949x over previous
#include <cuda_runtime.h>
#include <cuda_fp16.h>
#include <cstdint>

#define BB 2
#define TT 2048
#define CCH 1024
#define HH 16
#define DD 64
#define MTOK (BB*TT)          // 4096 tokens
#define GK   1024

// ---------------------------------------------------------------------------
// Scratch (allocation-free rule: __device__ globals), fp16 single-precision
// ---------------------------------------------------------------------------
__device__ __half g_hs_h[MTOK*CCH];
__device__ __half g_Wqk_h[CCH*CCH];
__device__ __half g_Wv_h [CCH*CCH];
__device__ __half g_Wo_h [CCH*CCH];
__device__ __half g_qk_h[MTOK*CCH];
__device__ __half g_v_h [MTOK*CCH];
__device__ __half g_y_h [MTOK*CCH];

// ===========================================================================
// Helpers
// ===========================================================================
__device__ __forceinline__ void mma_fp16(float c[4],
    const unsigned int a[4], const unsigned int b[2])
{
    asm volatile(
        "mma.sync.aligned.m16n8k16.row.col.f32.f16.f16.f32 "
        "{%0,%1,%2,%3}, {%4,%5,%6,%7}, {%8,%9}, {%0,%1,%2,%3};"
        : "+f"(c[0]), "+f"(c[1]), "+f"(c[2]), "+f"(c[3])
        : "r"(a[0]), "r"(a[1]), "r"(a[2]), "r"(a[3]), "r"(b[0]), "r"(b[1]));
}

__device__ __forceinline__ void ldsm4(const __half* base, int row0,
    int kc, int lane, int stride, unsigned int r[4])
{
    const __half* p = base + (row0 + (lane & 15)) * stride
                           + kc + ((lane >> 4) << 3);
    unsigned int addr = (unsigned int)__cvta_generic_to_shared(p);
    asm volatile("ldmatrix.sync.aligned.m8n8.x4.shared.b16 {%0,%1,%2,%3}, [%4];"
        : "=r"(r[0]), "=r"(r[1]), "=r"(r[2]), "=r"(r[3]) : "r"(addr));
}

__device__ __forceinline__ void ldsm2(const __half* base, int row0,
    int kc, int lane, int stride, unsigned int r[2])
{
    const __half* p = base + (row0 + (lane & 7)) * stride
                           + kc + (((lane >> 3) & 1) << 3);
    unsigned int addr = (unsigned int)__cvta_generic_to_shared(p);
    asm volatile("ldmatrix.sync.aligned.m8n8.x2.shared.b16 {%0,%1}, [%2];"
        : "=r"(r[0]), "=r"(r[1]) : "r"(addr));
}

// transposed B-fragment load: smem tile is [k][n] row-major (rows = k)
__device__ __forceinline__ void ldsm2t(const __half* base, int k0,
    int n0, int lane, int stride, unsigned int r[2])
{
    const __half* p = base
        + (k0 + (lane & 7) + ((lane >> 3) & 1) * 8) * stride + n0;
    unsigned int addr = (unsigned int)__cvta_generic_to_shared(p);
    asm volatile("ldmatrix.sync.aligned.m8n8.x2.trans.shared.b16 {%0,%1}, [%2];"
        : "=r"(r[0]), "=r"(r[1]) : "r"(addr));
}

// ===========================================================================
// Fused downcast fp32 -> fp16: hs + 3 weight matrices
// ===========================================================================
#define N4_HS (MTOK*CCH/4)
#define N4_W  (CCH*CCH/4)
#define N4_TOT (N4_HS + 3*N4_W)

__global__ void downcast_kernel(
    const float4* __restrict__ hs, const float4* __restrict__ wqk,
    const float4* __restrict__ wv, const float4* __restrict__ wo,
    __half2* __restrict__ hs_h, __half2* __restrict__ wqk_h,
    __half2* __restrict__ wv_h, __half2* __restrict__ wo_h)
{
    int i = blockIdx.x * blockDim.x + threadIdx.x;
    if (i >= N4_TOT) return;
    const float4* src; __half2* dh; int off;
    if (i < N4_HS)            { src = hs;  dh = hs_h;  off = i; }
    else if (i < N4_HS+N4_W)  { src = wqk; dh = wqk_h; off = i - N4_HS; }
    else if (i < N4_HS+2*N4_W){ src = wv;  dh = wv_h;  off = i - N4_HS - N4_W; }
    else                      { src = wo;  dh = wo_h;  off = i - N4_HS - 2*N4_W; }
    float4 v = src[off];
    dh[2*off    ] = __halves2half2(__float2half_rn(v.x), __float2half_rn(v.y));
    dh[2*off + 1] = __halves2half2(__float2half_rn(v.z), __float2half_rn(v.w));
}

// ===========================================================================
// fp16 1-term tensor-core GEMM: C = Ah@Wh^T + bias.
// CTA 128x128, BK=32, 256 threads (8 warps, 64x32 warp tiles), cp.async x2.
// Output: fp32 Cout (if non-null) else fp16 outh.
// ===========================================================================
#define SSTR 40
#define KTILE (128*SSTR)
#define STAGE_ELEMS (2*KTILE)           // A, W
#define GEMM_SMEM (2*STAGE_ELEMS*2)     // 40960 bytes

__global__ __launch_bounds__(256, 2) void gemm_fp16_kernel(
    const __half* __restrict__ Ah_g, const __half* __restrict__ Wh_g,
    const float* __restrict__ bias, float* __restrict__ Cout,
    __half* __restrict__ outh)
{
    extern __shared__ __half smem[];

    const int tid  = threadIdx.x;
    const int wid  = tid >> 5;
    const int lane = tid & 31;
    const int g    = lane >> 2;
    const int t4   = lane & 3;
    const int m0   = blockIdx.y * 128;
    const int n0   = blockIdx.x * 128;
    const int wm   = (wid & 1) * 64;
    const int wn   = (wid >> 1) * 32;

    float acc[4][4][4];
#pragma unroll
    for (int i = 0; i < 4; i++)
#pragma unroll
        for (int j = 0; j < 4; j++)
#pragma unroll
            for (int r = 0; r < 4; r++) acc[i][j][r] = 0.f;

    auto issue_stage = [&](int kt, int s) {
        const int kk = kt * 32;
#pragma unroll
        for (int p = 0; p < 4; p++) {
            int idx  = tid + 256*p;          // 0..1023
            int tile = idx >> 9;             // 0: A, 1: W
            int rem  = idx & 511;
            int r    = rem >> 2;             // 0..127
            int c    = rem & 3;              // 16B chunks
            const __half* sb = tile ? Wh_g : Ah_g;
            int grow = (tile ? n0 : m0) + r;
            const __half* src = sb + (size_t)grow * GK + kk + c*8;
            __half* dst = smem + s*STAGE_ELEMS + tile*KTILE + r*SSTR + c*8;
            unsigned int daddr = (unsigned int)__cvta_generic_to_shared(dst);
            asm volatile("cp.async.cg.shared.global [%0], [%1], 16;\n"
                         :: "r"(daddr), "l"(src));
        }
        asm volatile("cp.async.commit_group;\n");
    };

    issue_stage(0, 0);

    const int nk = GK / 32;
    for (int kt = 0; kt < nk; kt++) {
        const int s = kt & 1;
        const bool more = (kt + 1 < nk);
        if (more) {
            issue_stage(kt + 1, s ^ 1);
            asm volatile("cp.async.wait_group 1;\n");
        } else {
            asm volatile("cp.async.wait_group 0;\n");
        }
        __syncthreads();

        const __half* sAh = smem + s*STAGE_ELEMS;
        const __half* sWh = sAh + KTILE;

#pragma unroll
        for (int ks = 0; ks < 32; ks += 16) {
            unsigned int ah[4][4], bh[4][2];
#pragma unroll
            for (int i = 0; i < 4; i++)
                ldsm4(sAh, wm + i*16, ks, lane, SSTR, ah[i]);
#pragma unroll
            for (int j = 0; j < 4; j++)
                ldsm2(sWh, wn + j*8, ks, lane, SSTR, bh[j]);
#pragma unroll
            for (int i = 0; i < 4; i++)
#pragma unroll
                for (int j = 0; j < 4; j++)
                    mma_fp16(acc[i][j], ah[i], bh[j]);
        }
        __syncthreads();
    }

    // epilogue
#pragma unroll
    for (int i = 0; i < 4; i++)
#pragma unroll
        for (int j = 0; j < 4; j++) {
            const int r = m0 + wm + i*16 + g;
            const int c = n0 + wn + j*8 + t4*2;
            const float b0v = bias[c], b1v = bias[c+1];
            float v00 = acc[i][j][0] + b0v, v01 = acc[i][j][1] + b1v;
            float v10 = acc[i][j][2] + b0v, v11 = acc[i][j][3] + b1v;
            if (Cout) {
                float2 w0 = {v00, v01}, w1 = {v10, v11};
                *(float2*)&Cout[(size_t)r       * CCH + c] = w0;
                *(float2*)&Cout[(size_t)(r + 8) * CCH + c] = w1;
            } else {
                *(__half2*)&outh[(size_t)r      *CCH + c] =
                    __halves2half2(__float2half_rn(v00), __float2half_rn(v01));
                *(__half2*)&outh[(size_t)(r + 8)*CCH + c] =
                    __halves2half2(__float2half_rn(v10), __float2half_rn(v11));
            }
        }
}

// ===========================================================================
// fp16 flash attention, minimal-mma: S = Qh@Kh^T (1 mma), PV = 1 mma.
// CTA: 64 queries x one (b,h), 4 warps. Smem: Qh,Kh,Vh = 27 KB.
// Heavy-first ordering (qi reversed) to shrink causal-imbalance tail.
// ===========================================================================
#define ASTR 72
#define ATILE (64*ASTR)
#define ATTN_SMEM (3*ATILE*2)     // 27648 bytes

__global__ __launch_bounds__(128) void attn_mma_kernel(
    const __half* __restrict__ qkh, const __half* __restrict__ vgh,
    __half* __restrict__ yh)
{
    extern __shared__ __half smA[];
    __half* Qh = smA;
    __half* Kh = smA +   ATILE;
    __half* Vh = smA + 2*ATILE;   // [t][d]

    const int tid  = threadIdx.x;
    const int wid  = tid >> 5;
    const int lane = tid & 31;
    const int g    = lane >> 2;
    const int t4   = lane & 3;
    const int qi = (TT/64 - 1) - blockIdx.x;    // heavy first
    const int bh = blockIdx.y;
    const int b  = bh / HH, h = bh % HH;
    const int q0 = qi * 64;
    const size_t base = ((size_t)b * TT) * CCH + (size_t)h * DD;

    // ---- load Q tile ----
#pragma unroll
    for (int p = 0; p < 4; p++) {
        int idx = tid + 128*p;           // 0..511
        int r   = idx >> 3;              // 0..63
        int c8  = (idx & 7) * 8;         // 0..56
        size_t gg = base + (size_t)(q0 + r)*CCH + c8;
        *(uint4*)&Qh[r*ASTR + c8] = *(const uint4*)&qkh[gg];
    }

    float m0r = -1e30f, m1r = -1e30f, l0r = 0.f, l1r = 0.f;
    float o[8][4];
#pragma unroll
    for (int j = 0; j < 8; j++)
#pragma unroll
        for (int r = 0; r < 4; r++) o[j][r] = 0.f;

    for (int kv = 0; kv <= qi; kv++) {
        __syncthreads();   // prior-iter readers done (first iter covers Q fill)
#pragma unroll
        for (int p = 0; p < 8; p++) {
            int idx  = tid + 128*p;          // 0..1023
            int tile = idx >> 9;             // 0: K, 1: V
            int rem  = idx & 511;
            int r    = rem >> 3;
            int c8   = (rem & 7) * 8;
            size_t gg = base + (size_t)(kv*64 + r)*CCH + c8;
            __half* dst = tile ? Vh : Kh;
            const __half* src = tile ? vgh : qkh;
            *(uint4*)&dst[r*ASTR + c8] = *(const uint4*)&src[gg];
        }
        __syncthreads();

        // ---- S = Qh @ Kh^T (1 mma per tile) ----
        float s[8][4];
#pragma unroll
        for (int j = 0; j < 8; j++)
#pragma unroll
            for (int r = 0; r < 4; r++) s[j][r] = 0.f;

#pragma unroll
        for (int ks = 0; ks < 4; ks++) {
            unsigned int ah[4];
            ldsm4(Qh, wid*16, ks*16, lane, ASTR, ah);
#pragma unroll
            for (int j = 0; j < 8; j++) {
                unsigned int kbh[2];
                ldsm2(Kh, j*8, ks*16, lane, ASTR, kbh);
                mma_fp16(s[j], ah, kbh);
            }
        }

        // ---- scale + causal mask ----
        const float scale = 0.125f;
        const int row0 = wid*16 + g;
        const int row1 = row0 + 8;
        if (kv == qi) {
#pragma unroll
            for (int j = 0; j < 8; j++) {
                const int c0 = j*8 + 2*t4, c1 = c0 + 1;
                s[j][0] = (c0 > row0) ? -1e30f : s[j][0]*scale;
                s[j][1] = (c1 > row0) ? -1e30f : s[j][1]*scale;
                s[j][2] = (c0 > row1) ? -1e30f : s[j][2]*scale;
                s[j][3] = (c1 > row1) ? -1e30f : s[j][3]*scale;
            }
        } else {
#pragma unroll
            for (int j = 0; j < 8; j++)
#pragma unroll
                for (int r = 0; r < 4; r++) s[j][r] *= scale;
        }

        // ---- online softmax (quad reductions) ----
        float mx0 = -1e30f, mx1 = -1e30f;
#pragma unroll
        for (int j = 0; j < 8; j++) {
            mx0 = fmaxf(mx0, fmaxf(s[j][0], s[j][1]));
            mx1 = fmaxf(mx1, fmaxf(s[j][2], s[j][3]));
        }
        mx0 = fmaxf(mx0, __shfl_xor_sync(0xffffffffu, mx0, 1));
        mx0 = fmaxf(mx0, __shfl_xor_sync(0xffffffffu, mx0, 2));
        mx1 = fmaxf(mx1, __shfl_xor_sync(0xffffffffu, mx1, 1));
        mx1 = fmaxf(mx1, __shfl_xor_sync(0xffffffffu, mx1, 2));

        const float mn0 = fmaxf(m0r, mx0), mn1 = fmaxf(m1r, mx1);
        const float cr0 = __expf(m0r - mn0), cr1 = __expf(m1r - mn1);
        m0r = mn0; m1r = mn1;

        float sum0 = 0.f, sum1 = 0.f;
#pragma unroll
        for (int j = 0; j < 8; j++) {
            s[j][0] = __expf(s[j][0] - mn0);
            s[j][1] = __expf(s[j][1] - mn0);
            s[j][2] = __expf(s[j][2] - mn1);
            s[j][3] = __expf(s[j][3] - mn1);
            sum0 += s[j][0] + s[j][1];
            sum1 += s[j][2] + s[j][3];
        }
        sum0 += __shfl_xor_sync(0xffffffffu, sum0, 1);
        sum0 += __shfl_xor_sync(0xffffffffu, sum0, 2);
        sum1 += __shfl_xor_sync(0xffffffffu, sum1, 1);
        sum1 += __shfl_xor_sync(0xffffffffu, sum1, 2);
        l0r = l0r*cr0 + sum0;
        l1r = l1r*cr1 + sum1;

#pragma unroll
        for (int j = 0; j < 8; j++) {
            o[j][0] *= cr0; o[j][1] *= cr0;
            o[j][2] *= cr1; o[j][3] *= cr1;
        }

        // ---- O += P @ V (1 mma) ----
#pragma unroll
        for (int c = 0; c < 4; c++) {
            unsigned int aPh[4];
#pragma unroll
            for (int half = 0; half < 2; half++) {
                const int jt = 2*c + half;
                __half2 P01 = __halves2half2(__float2half_rn(s[jt][0]),
                                             __float2half_rn(s[jt][1]));
                __half2 P23 = __halves2half2(__float2half_rn(s[jt][2]),
                                             __float2half_rn(s[jt][3]));
                aPh[2*half    ] = *(unsigned int*)&P01;
                aPh[2*half + 1] = *(unsigned int*)&P23;
            }
#pragma unroll
            for (int j = 0; j < 8; j++) {
                unsigned int vbh[2];
                ldsm2t(Vh, c*16, j*8, lane, ASTR, vbh);
                mma_fp16(o[j], aPh, vbh);
            }
        }
    }

    // ---- normalize + write y as fp16 ----
    const float inv0 = 1.f / l0r, inv1 = 1.f / l1r;
    const int r0 = q0 + wid*16 + g;
    const int r1 = r0 + 8;
#pragma unroll
    for (int j = 0; j < 8; j++) {
        const int c = j*8 + 2*t4;
        *(__half2*)&yh[base + (size_t)r0*CCH + c] =
            __halves2half2(__float2half_rn(o[j][0]*inv0),
                           __float2half_rn(o[j][1]*inv0));
        *(__half2*)&yh[base + (size_t)r1*CCH + c] =
            __halves2half2(__float2half_rn(o[j][2]*inv1),
                           __float2half_rn(o[j][3]*inv1));
    }
}

// ---------------------------------------------------------------------------
extern "C" void kernel_launch(void* const* d_in, const int* in_sizes, int n_in,
                              void* d_out, int out_size)
{
    const float* hs  = (const float*)d_in[0];
    const float* Wqk = (const float*)d_in[1];
    const float* bqk = (const float*)d_in[2];
    const float* Wv  = (const float*)d_in[3];
    const float* bv  = (const float*)d_in[4];
    const float* Wo  = (const float*)d_in[5];
    const float* bo  = (const float*)d_in[6];
    float* out = (float*)d_out;

    __half *hs_h,*wqk_h,*wv_h,*wo_h,*qk_h,*v_h,*y_h;
    cudaGetSymbolAddress((void**)&hs_h, g_hs_h);
    cudaGetSymbolAddress((void**)&wqk_h, g_Wqk_h);
    cudaGetSymbolAddress((void**)&wv_h, g_Wv_h);
    cudaGetSymbolAddress((void**)&wo_h, g_Wo_h);
    cudaGetSymbolAddress((void**)&qk_h, g_qk_h);
    cudaGetSymbolAddress((void**)&v_h, g_v_h);
    cudaGetSymbolAddress((void**)&y_h, g_y_h);

    cudaFuncSetAttribute(attn_mma_kernel,
                         cudaFuncAttributeMaxDynamicSharedMemorySize, ATTN_SMEM);
    cudaFuncSetAttribute(gemm_fp16_kernel,
                         cudaFuncAttributeMaxDynamicSharedMemorySize, GEMM_SMEM);

    // fused downcast of all fp32 inputs
    downcast_kernel<<<(N4_TOT+255)/256, 256>>>(
        (const float4*)hs, (const float4*)Wqk, (const float4*)Wv, (const float4*)Wo,
        (__half2*)hs_h, (__half2*)wqk_h, (__half2*)wv_h, (__half2*)wo_h);

    dim3 ggrid(CCH/128, MTOK/128);   // (8, 32)
    gemm_fp16_kernel<<<ggrid, 256, GEMM_SMEM>>>(hs_h, wqk_h, bqk, nullptr, qk_h);
    gemm_fp16_kernel<<<ggrid, 256, GEMM_SMEM>>>(hs_h, wv_h,  bv,  nullptr, v_h);

    attn_mma_kernel<<<dim3(TT/64, BB*HH), 128, ATTN_SMEM>>>(qk_h, v_h, y_h);

    gemm_fp16_kernel<<<ggrid, 256, GEMM_SMEM>>>(y_h, wo_h, bo, out, nullptr);
}